// round 16
// baseline (speedup 1.0000x reference)
#include <cuda_runtime.h>
#include <cuda_bf16.h>
#include <cstdint>
#include <math.h>

#define BB 16384
#define DD 4096
#define HH 128

// ---------------- scratch ----------------
__device__ __nv_bfloat16 g_xb[(size_t)BB * DD];     // visible sample (in-place chain)
__device__ __nv_bfloat16 g_hb[(size_t)BB * HH];     // hidden sample
__device__ float         g_lin[(size_t)BB * DD];    // x-pass pre-activation scratch
__device__ __nv_bfloat16 g_Wx[2][(size_t)DD * HH];  // W splits, [d][h] (x-pass B)
__device__ __nv_bfloat16 g_Wh[2][(size_t)DD * HH];  // W splits, [h][d] (h-pass B)
__device__ double g_acc[4];

// ---------------- threefry2x32 (JAX-exact, verified R1-R15) ----------------
__host__ __device__ __forceinline__ uint32_t rotl32(uint32_t v, int s) {
  return (v << s) | (v >> (32 - s));
}
__host__ __device__ __forceinline__ void tf2x32(uint32_t k0, uint32_t k1,
                                                uint32_t x0, uint32_t x1,
                                                uint32_t &o0, uint32_t &o1) {
  uint32_t ks2 = k0 ^ k1 ^ 0x1BD11BDAu;
  x0 += k0; x1 += k1;
#define TF_R(r) { x0 += x1; x1 = rotl32(x1, r); x1 ^= x0; }
  TF_R(13) TF_R(15) TF_R(26) TF_R(6)   x0 += k1;  x1 += ks2 + 1u;
  TF_R(17) TF_R(29) TF_R(16) TF_R(24)  x0 += ks2; x1 += k0 + 2u;
  TF_R(13) TF_R(15) TF_R(26) TF_R(6)   x0 += k0;  x1 += k1 + 3u;
  TF_R(17) TF_R(29) TF_R(16) TF_R(24)  x0 += k1;  x1 += ks2 + 4u;
  TF_R(13) TF_R(15) TF_R(26) TF_R(6)   x0 += ks2; x1 += k0 + 5u;
#undef TF_R
  o0 = x0; o1 = x1;
}
__device__ __forceinline__ float jax_uniform01(uint32_t k0, uint32_t k1, uint32_t idx) {
  uint32_t a, b;
  tf2x32(k0, k1, 0u, idx, a, b);
  uint32_t bits = a ^ b;
  return __uint_as_float((bits >> 9) | 0x3F800000u) - 1.0f;
}
__device__ __forceinline__ float fast_sigmoid(float x) {
  float e, r;
  asm("ex2.approx.f32 %0, %1;" : "=f"(e) : "f"(-1.4426950408889634f * x));
  asm("rcp.approx.f32 %0, %1;" : "=f"(r) : "f"(1.0f + e));
  return r;
}
__device__ __forceinline__ float softplusf_(float x) {
  return fmaxf(x, 0.0f) + log1pf(expf(-fabsf(x)));
}

// ---------------- PTX helpers (baseline sm_100-safe) ----------------
__device__ __forceinline__ uint32_t smem_u32(const void *p) {
  uint32_t a;
  asm("{ .reg .u64 t; cvta.to.shared.u64 t, %1; cvt.u32.u64 %0, t; }"
      : "=r"(a) : "l"(p));
  return a;
}
__device__ __forceinline__ void ldsm4(uint32_t *r, uint32_t a) {
  asm volatile("ldmatrix.sync.aligned.m8n8.x4.shared.b16 {%0,%1,%2,%3}, [%4];"
               : "=r"(r[0]), "=r"(r[1]), "=r"(r[2]), "=r"(r[3]) : "r"(a));
}
__device__ __forceinline__ void mma_bf16(float *c, const uint32_t *a,
                                         uint32_t b0, uint32_t b1) {
  asm volatile(
      "mma.sync.aligned.m16n8k16.row.col.f32.bf16.bf16.f32 "
      "{%0,%1,%2,%3}, {%4,%5,%6,%7}, {%8,%9}, {%0,%1,%2,%3};"
      : "+f"(c[0]), "+f"(c[1]), "+f"(c[2]), "+f"(c[3])
      : "r"(a[0]), "r"(a[1]), "r"(a[2]), "r"(a[3]), "r"(b0), "r"(b1));
}
__device__ __forceinline__ uint32_t sw128(uint32_t o) {
  return o ^ ((o >> 3) & 0x70);
}

// load [ROWS x 64 bf16] tile, 128B rows, SW128-swizzled, via cp.async
template <int LD, int ROWS>
__device__ __forceinline__ void load_tile(uint32_t sdst, const __nv_bfloat16 *g,
                                          int row0, int kt) {
  int t = threadIdx.x;
#pragma unroll
  for (int i = 0; i < ROWS / 32; i++) {
    int idx = t + 256 * i;
    int r = idx >> 3, c = idx & 7;
    uint32_t sw = sw128((uint32_t)(r * 128 + c * 16));
    const void *ga = (const void *)(g + (size_t)(row0 + r) * LD + kt + c * 8);
    asm volatile("cp.async.cg.shared.global [%0], [%1], 16;"
                 :: "r"(sdst + sw), "l"(ga));
  }
}

// =============================================================
// h-pass (R5/R13 config, unchanged): lin = x @ W + bh
// M=16384 N=128 K=4096 (2 splits); CTA 64x128, BK=64, 2 CTAs/SM.
// =============================================================
static constexpr int H_STAGE = 40960;
static constexpr int H_SMEM = 2 * H_STAGE;  // 81920

__global__ void __launch_bounds__(256, 2)
gemm_h_kernel(const float *__restrict__ bh_, uint32_t k0, uint32_t k1,
              int do_sample, int acc_slot) {
  extern __shared__ char smem[];
  uint32_t sb = smem_u32(smem);
  const int t = threadIdx.x, wid = t >> 5, l = t & 31;
  const int wm = wid & 1, wn = wid >> 1;
  const int m0 = blockIdx.x * 64;
  const int q = l >> 2, tq = l & 3;

  uint32_t offA[2], offB[2];
#pragma unroll
  for (int i = 0; i < 2; i++)
    offA[i] = (uint32_t)((wm * 32 + i * 16 + (l & 15)) * 128 + ((l >> 4) & 1) * 16);
#pragma unroll
  for (int jb = 0; jb < 2; jb++)
    offB[jb] = (uint32_t)((wn * 32 + jb * 16 + (l & 7) + ((l >> 4) & 1) * 8) * 128 +
                          ((l >> 3) & 1) * 16);

  float acc[2][4][4];
#pragma unroll
  for (int i = 0; i < 2; i++)
#pragma unroll
    for (int j = 0; j < 4; j++)
#pragma unroll
      for (int v = 0; v < 4; v++) acc[i][j][v] = 0.0f;

  auto issue_load = [&](int c) {
    int s = c & 1, kt = c * 64;
    uint32_t base = sb + s * H_STAGE;
    load_tile<DD, 64>(base, g_xb, m0, kt);
#pragma unroll
    for (int p = 0; p < 2; p++)
      load_tile<DD, 128>(base + 8192 + 16384 * p, g_Wh[p], 0, kt);
    asm volatile("cp.async.commit_group;" ::: "memory");
  };

  issue_load(0); issue_load(1);

#pragma unroll 1
  for (int c = 0; c < 64; c++) {
    if (c + 1 < 64) asm volatile("cp.async.wait_group 1;" ::: "memory");
    else            asm volatile("cp.async.wait_group 0;" ::: "memory");
    __syncthreads();
    uint32_t base = sb + (uint32_t)(c & 1) * H_STAGE;
#pragma unroll
    for (int kk = 0; kk < 4; kk++) {
      uint32_t a[2][4];
#pragma unroll
      for (int i = 0; i < 2; i++)
        ldsm4(a[i], base + sw128(offA[i] + kk * 32));
#pragma unroll
      for (int p = 0; p < 2; p++) {
        uint32_t bb = base + 8192u + 16384u * p;
#pragma unroll
        for (int jb = 0; jb < 2; jb++) {
          uint32_t b[4];
          ldsm4(b, bb + sw128(offB[jb] + kk * 32));
#pragma unroll
          for (int i = 0; i < 2; i++) {
            mma_bf16(acc[i][jb * 2 + 0], a[i], b[0], b[1]);
            mma_bf16(acc[i][jb * 2 + 1], a[i], b[2], b[3]);
          }
        }
      }
    }
    __syncthreads();
    if (c + 2 < 64) issue_load(c + 2);
  }

  // epilogue: bias + softplus and/or threefry sample into g_hb
  double sp = 0.0;
  const __nv_bfloat16 onev = __float2bfloat16(1.0f);
  const __nv_bfloat16 zerov = __float2bfloat16(0.0f);
#pragma unroll
  for (int i = 0; i < 2; i++) {
#pragma unroll
    for (int j = 0; j < 4; j++) {
      int col = wn * 32 + j * 8 + 2 * tq;
      float2 b2 = *(const float2 *)&bh_[col];
#pragma unroll
      for (int h = 0; h < 2; h++) {
        int gr = m0 + wm * 32 + i * 16 + q + h * 8;
        float l0 = acc[i][j][2 * h + 0] + b2.x;
        float l1 = acc[i][j][2 * h + 1] + b2.y;
        if (acc_slot >= 0)
          sp += (double)softplusf_(l0) + (double)softplusf_(l1);
        if (do_sample) {
          float p0 = fast_sigmoid(l0), p1 = fast_sigmoid(l1);
          uint32_t idx0 = (uint32_t)gr * (uint32_t)HH + (uint32_t)col;
          float u0 = jax_uniform01(k0, k1, idx0);
          float u1 = jax_uniform01(k0, k1, idx0 + 1u);
          __nv_bfloat162 v;
          v.x = (u0 < p0) ? onev : zerov;
          v.y = (u1 < p1) ? onev : zerov;
          *(__nv_bfloat162 *)&g_hb[(size_t)gr * HH + col] = v;
        }
      }
    }
  }
  if (acc_slot >= 0) {
#pragma unroll
    for (int o = 16; o > 0; o >>= 1) sp += __shfl_down_sync(0xffffffffu, sp, o);
    if (l == 0) atomicAdd(&g_acc[acc_slot], sp);
  }
}

// =============================================================
// x-pass GEMM: g_lin = h @ W^T + bx   M=16384 N=4096 K=128 (2 splits)
// CTA 64(M) x 128(N); all loads upfront; 2 CTAs/SM; pure tensor kernel.
// smem: A 2x8KB @0; B @16384: chunk kc @+kc*32768, split p @+p*16384. 80KB.
// =============================================================
static constexpr int XG_SMEM = 81920;

__global__ void __launch_bounds__(256, 2)
gemm_x_kernel(const float *__restrict__ bx_) {
  extern __shared__ char smem[];
  uint32_t sb = smem_u32(smem);
  const int t = threadIdx.x, wid = t >> 5, l = t & 31;
  const int wm = wid & 1, wn = wid >> 1;
  const int m0 = blockIdx.x * 64, n0 = blockIdx.y * 128;
  const int q = l >> 2, tq = l & 3;

  uint32_t offA[2], offB[2];
#pragma unroll
  for (int i = 0; i < 2; i++)
    offA[i] = (uint32_t)((wm * 32 + i * 16 + (l & 15)) * 128 + ((l >> 4) & 1) * 16);
#pragma unroll
  for (int jb = 0; jb < 2; jb++)
    offB[jb] = (uint32_t)((wn * 32 + jb * 16 + (l & 7) + ((l >> 4) & 1) * 8) * 128 +
                          ((l >> 3) & 1) * 16);

  // all loads upfront (K=128 -> 2 chunks)
#pragma unroll
  for (int kc = 0; kc < 2; kc++) {
    load_tile<HH, 64>(sb + kc * 8192, g_hb, m0, kc * 64);
#pragma unroll
    for (int p = 0; p < 2; p++)
      load_tile<HH, 128>(sb + 16384 + kc * 32768 + p * 16384, g_Wx[p],
                         n0, kc * 64);
  }
  asm volatile("cp.async.commit_group;" ::: "memory");

  float acc[2][4][4];
#pragma unroll
  for (int i = 0; i < 2; i++)
#pragma unroll
    for (int j = 0; j < 4; j++)
#pragma unroll
      for (int v = 0; v < 4; v++) acc[i][j][v] = 0.0f;

  asm volatile("cp.async.wait_group 0;" ::: "memory");
  __syncthreads();

#pragma unroll
  for (int kc = 0; kc < 2; kc++) {
    uint32_t abase = sb + (uint32_t)kc * 8192;
    uint32_t bbase = sb + 16384u + (uint32_t)kc * 32768;
#pragma unroll
    for (int kk = 0; kk < 4; kk++) {
      uint32_t a[2][4];
#pragma unroll
      for (int i = 0; i < 2; i++)
        ldsm4(a[i], abase + sw128(offA[i] + kk * 32));
#pragma unroll
      for (int p = 0; p < 2; p++) {
        uint32_t bb = bbase + p * 16384u;
#pragma unroll
        for (int jb = 0; jb < 2; jb++) {
          uint32_t b[4];
          ldsm4(b, bb + sw128(offB[jb] + kk * 32));
#pragma unroll
          for (int i = 0; i < 2; i++) {
            mma_bf16(acc[i][jb * 2 + 0], a[i], b[0], b[1]);
            mma_bf16(acc[i][jb * 2 + 1], a[i], b[2], b[3]);
          }
        }
      }
    }
  }

  // epilogue: bias add (same fp32 op as before) + store lin
#pragma unroll
  for (int i = 0; i < 2; i++) {
#pragma unroll
    for (int j = 0; j < 4; j++) {
      int col = n0 + wn * 32 + j * 8 + 2 * tq;
      float2 b2 = *(const float2 *)&bx_[col];
#pragma unroll
      for (int h = 0; h < 2; h++) {
        int row = m0 + wm * 32 + i * 16 + q + h * 8;
        float2 v;
        v.x = acc[i][j][2 * h + 0] + b2.x;
        v.y = acc[i][j][2 * h + 1] + b2.y;
        *(float2 *)&g_lin[(size_t)row * DD + col] = v;
      }
    }
  }
}

// =============================================================
// x-pass sampler: pure streaming threefry. No smem, no syncs.
// Each thread: one float4 of lin -> 4 samples -> one 8B store.
// =============================================================
__global__ void __launch_bounds__(256)
sample_x_kernel(const float *__restrict__ bx_, uint32_t k0, uint32_t k1,
                int bx_slot) {
  size_t n4 = (size_t)BB * DD / 4;
  double spb = 0.0;
  for (size_t i = (size_t)blockIdx.x * blockDim.x + threadIdx.x; i < n4;
       i += (size_t)gridDim.x * blockDim.x) {
    float4 lv = ((const float4 *)g_lin)[i];
    uint32_t idx = (uint32_t)(i * 4);
    float u0 = jax_uniform01(k0, k1, idx);
    float u1 = jax_uniform01(k0, k1, idx + 1u);
    float u2 = jax_uniform01(k0, k1, idx + 2u);
    float u3 = jax_uniform01(k0, k1, idx + 3u);
    bool s0 = u0 < fast_sigmoid(lv.x);
    bool s1 = u1 < fast_sigmoid(lv.y);
    bool s2 = u2 < fast_sigmoid(lv.z);
    bool s3 = u3 < fast_sigmoid(lv.w);
    if (bx_slot >= 0) {
      uint32_t d = idx & (DD - 1);
      if (s0) spb += (double)bx_[d];
      if (s1) spb += (double)bx_[d + 1];
      if (s2) spb += (double)bx_[d + 2];
      if (s3) spb += (double)bx_[d + 3];
    }
    uint2 o;
    o.x = (s0 ? 0x3F80u : 0u) | (s1 ? 0x3F800000u : 0u);
    o.y = (s2 ? 0x3F80u : 0u) | (s3 ? 0x3F800000u : 0u);
    ((uint2 *)g_xb)[i] = o;
  }
  if (bx_slot >= 0) {
#pragma unroll
    for (int o = 16; o > 0; o >>= 1) spb += __shfl_down_sync(0xffffffffu, spb, o);
    if ((threadIdx.x & 31) == 0) atomicAdd(&g_acc[bx_slot], spb);
  }
}

// ---------------- prep: conv (+x.bx) and wsplit merged ----------------
__global__ void prep_kernel(const float *__restrict__ x,
                            const float *__restrict__ bx,
                            const float *__restrict__ W) {
  if (blockIdx.x < 1024) {
    size_t n = (size_t)BB * DD / 4;
    double s = 0.0;
    for (size_t i = (size_t)blockIdx.x * blockDim.x + threadIdx.x; i < n;
         i += (size_t)1024 * blockDim.x) {
      float4 v = ((const float4 *)x)[i];
      ushort4 o;
      o.x = __bfloat16_as_ushort(__float2bfloat16(v.x));
      o.y = __bfloat16_as_ushort(__float2bfloat16(v.y));
      o.z = __bfloat16_as_ushort(__float2bfloat16(v.z));
      o.w = __bfloat16_as_ushort(__float2bfloat16(v.w));
      ((ushort4 *)g_xb)[i] = o;
      uint32_t d = (uint32_t)((i * 4) & (DD - 1));
      const float4 b4 = *(const float4 *)&bx[d];
      s += (double)(v.x * b4.x + v.y * b4.y) + (double)(v.z * b4.z + v.w * b4.w);
    }
#pragma unroll
    for (int off = 16; off > 0; off >>= 1)
      s += __shfl_down_sync(0xffffffffu, s, off);
    if ((threadIdx.x & 31) == 0) atomicAdd(&g_acc[2], s);
  } else {
    int n = DD * HH;
    for (int i = (blockIdx.x - 1024) * blockDim.x + threadIdx.x; i < n;
         i += 256 * blockDim.x) {
      float w = W[i];
      __nv_bfloat16 b0 = __float2bfloat16(w);
      float r1 = w - __bfloat162float(b0);
      __nv_bfloat16 b1 = __float2bfloat16(r1);
      g_Wx[0][i] = b0; g_Wx[1][i] = b1;
      int d = i >> 7, h = i & 127;
      int j = h * DD + d;
      g_Wh[0][j] = b0; g_Wh[1][j] = b1;
    }
  }
}

__global__ void zero_acc_kernel() {
  if (threadIdx.x < 4) g_acc[threadIdx.x] = 0.0;
}

// cd = meanF(x) - meanF(x_rec); F = -sum softplus - v.bx
__global__ void finalize_kernel(float *out) {
  double cd = (-g_acc[0] - g_acc[2] + g_acc[1] + g_acc[3]) / (double)BB;
  out[0] = (float)cd;
}

// =============================================================
extern "C" void kernel_launch(void *const *d_in, const int *in_sizes, int n_in,
                              void *d_out, int out_size) {
  (void)in_sizes; (void)n_in; (void)out_size;
  const float *x  = (const float *)d_in[0];
  const float *W  = (const float *)d_in[1];
  const float *bx = (const float *)d_in[2];
  const float *bh = (const float *)d_in[3];

  static int attr_set = 0;
  if (!attr_set) {
    cudaFuncSetAttribute(gemm_h_kernel,
                         cudaFuncAttributeMaxDynamicSharedMemorySize, H_SMEM);
    cudaFuncSetAttribute(gemm_x_kernel,
                         cudaFuncAttributeMaxDynamicSharedMemorySize, XG_SMEM);
    attr_set = 1;
  }

  zero_acc_kernel<<<1, 32>>>();
  prep_kernel<<<1280, 256>>>(x, bx, W);

  dim3 grdh(BB / 64, 1);
  dim3 grdx(BB / 64, DD / 128);

  for (int i = 0; i < 4; i++) {
    uint32_t h0, h1, xk0, xk1;
    tf2x32(0u, 42u, 0u, (uint32_t)(2 * i),     h0,  h1);
    tf2x32(0u, 42u, 0u, (uint32_t)(2 * i + 1), xk0, xk1);
    gemm_h_kernel<<<grdh, 256, H_SMEM>>>(bh, h0, h1, /*sample=*/1,
                                         /*slot=*/(i == 0) ? 0 : -1);
    gemm_x_kernel<<<grdx, 256, XG_SMEM>>>(bx);
    sample_x_kernel<<<2048, 256>>>(bx, xk0, xk1,
                                   /*bx_slot=*/(i == 3) ? 3 : -1);
  }
  // F(x_rec) softplus term
  gemm_h_kernel<<<grdh, 256, H_SMEM>>>(bh, 0u, 0u, /*sample=*/0, /*slot=*/1);

  finalize_kernel<<<1, 1>>>((float *)d_out);
}

// round 17
// speedup vs baseline: 1.0644x; 1.0644x over previous
#include <cuda_runtime.h>
#include <cuda_bf16.h>
#include <cstdint>
#include <math.h>

#define BB 16384
#define DD 4096
#define HH 128
#define HALF (BB / 2)

// ---------------- scratch ----------------
__device__ __nv_bfloat16 g_xb[(size_t)BB * DD];     // visible sample (in-place chain)
__device__ __nv_bfloat16 g_hb[(size_t)BB * HH];     // hidden sample
__device__ __nv_bfloat16 g_Wx[2][(size_t)DD * HH];  // W splits, [d][h] (x-pass B)
__device__ __nv_bfloat16 g_Wh[2][(size_t)DD * HH];  // W splits, [h][d] (h-pass B)
__device__ double g_acc[4];

// ---------------- threefry2x32 (JAX-exact, verified R1-R16) ----------------
__host__ __device__ __forceinline__ uint32_t rotl32(uint32_t v, int s) {
  return (v << s) | (v >> (32 - s));
}
__host__ __device__ __forceinline__ void tf2x32(uint32_t k0, uint32_t k1,
                                                uint32_t x0, uint32_t x1,
                                                uint32_t &o0, uint32_t &o1) {
  uint32_t ks2 = k0 ^ k1 ^ 0x1BD11BDAu;
  x0 += k0; x1 += k1;
#define TF_R(r) { x0 += x1; x1 = rotl32(x1, r); x1 ^= x0; }
  TF_R(13) TF_R(15) TF_R(26) TF_R(6)   x0 += k1;  x1 += ks2 + 1u;
  TF_R(17) TF_R(29) TF_R(16) TF_R(24)  x0 += ks2; x1 += k0 + 2u;
  TF_R(13) TF_R(15) TF_R(26) TF_R(6)   x0 += k0;  x1 += k1 + 3u;
  TF_R(17) TF_R(29) TF_R(16) TF_R(24)  x0 += k1;  x1 += ks2 + 4u;
  TF_R(13) TF_R(15) TF_R(26) TF_R(6)   x0 += ks2; x1 += k0 + 5u;
#undef TF_R
  o0 = x0; o1 = x1;
}
__device__ __forceinline__ float jax_uniform01(uint32_t k0, uint32_t k1, uint32_t idx) {
  uint32_t a, b;
  tf2x32(k0, k1, 0u, idx, a, b);
  uint32_t bits = a ^ b;
  return __uint_as_float((bits >> 9) | 0x3F800000u) - 1.0f;
}
__device__ __forceinline__ float fast_sigmoid(float x) {
  float e, r;
  asm("ex2.approx.f32 %0, %1;" : "=f"(e) : "f"(-1.4426950408889634f * x));
  asm("rcp.approx.f32 %0, %1;" : "=f"(r) : "f"(1.0f + e));
  return r;
}
__device__ __forceinline__ float softplusf_(float x) {
  return fmaxf(x, 0.0f) + log1pf(expf(-fabsf(x)));
}

// ---------------- PTX helpers (baseline sm_100-safe) ----------------
__device__ __forceinline__ uint32_t smem_u32(const void *p) {
  uint32_t a;
  asm("{ .reg .u64 t; cvta.to.shared.u64 t, %1; cvt.u32.u64 %0, t; }"
      : "=r"(a) : "l"(p));
  return a;
}
__device__ __forceinline__ void ldsm4(uint32_t *r, uint32_t a) {
  asm volatile("ldmatrix.sync.aligned.m8n8.x4.shared.b16 {%0,%1,%2,%3}, [%4];"
               : "=r"(r[0]), "=r"(r[1]), "=r"(r[2]), "=r"(r[3]) : "r"(a));
}
__device__ __forceinline__ void mma_bf16(float *c, const uint32_t *a,
                                         uint32_t b0, uint32_t b1) {
  asm volatile(
      "mma.sync.aligned.m16n8k16.row.col.f32.bf16.bf16.f32 "
      "{%0,%1,%2,%3}, {%4,%5,%6,%7}, {%8,%9}, {%0,%1,%2,%3};"
      : "+f"(c[0]), "+f"(c[1]), "+f"(c[2]), "+f"(c[3])
      : "r"(a[0]), "r"(a[1]), "r"(a[2]), "r"(a[3]), "r"(b0), "r"(b1));
}
__device__ __forceinline__ uint32_t sw128(uint32_t o) {
  return o ^ ((o >> 3) & 0x70);
}

// load [ROWS x 64 bf16] tile, 128B rows, SW128-swizzled, via cp.async
template <int LD, int ROWS>
__device__ __forceinline__ void load_tile(uint32_t sdst, const __nv_bfloat16 *g,
                                          int row0, int kt) {
  int t = threadIdx.x;
#pragma unroll
  for (int i = 0; i < ROWS / 32; i++) {
    int idx = t + 256 * i;
    int r = idx >> 3, c = idx & 7;
    uint32_t sw = sw128((uint32_t)(r * 128 + c * 16));
    const void *ga = (const void *)(g + (size_t)(row0 + r) * LD + kt + c * 8);
    asm volatile("cp.async.cg.shared.global [%0], [%1], 16;"
                 :: "r"(sdst + sw), "l"(ga));
  }
}

// =============================================================
// h-pass (R5/R13 config + mbase): lin = x @ W + bh
// Half-grid 128 CTAs; CTA 64x128, BK=64, double-buffered, 2 CTAs/SM.
// =============================================================
static constexpr int H_STAGE = 40960;
static constexpr int H_SMEM = 2 * H_STAGE;  // 81920

__global__ void __launch_bounds__(256, 2)
gemm_h_kernel(const float *__restrict__ bh_, uint32_t k0, uint32_t k1,
              int do_sample, int acc_slot, int mbase) {
  extern __shared__ char smem[];
  uint32_t sb = smem_u32(smem);
  const int t = threadIdx.x, wid = t >> 5, l = t & 31;
  const int wm = wid & 1, wn = wid >> 1;
  const int m0 = mbase + blockIdx.x * 64;
  const int q = l >> 2, tq = l & 3;

  uint32_t offA[2], offB[2];
#pragma unroll
  for (int i = 0; i < 2; i++)
    offA[i] = (uint32_t)((wm * 32 + i * 16 + (l & 15)) * 128 + ((l >> 4) & 1) * 16);
#pragma unroll
  for (int jb = 0; jb < 2; jb++)
    offB[jb] = (uint32_t)((wn * 32 + jb * 16 + (l & 7) + ((l >> 4) & 1) * 8) * 128 +
                          ((l >> 3) & 1) * 16);

  float acc[2][4][4];
#pragma unroll
  for (int i = 0; i < 2; i++)
#pragma unroll
    for (int j = 0; j < 4; j++)
#pragma unroll
      for (int v = 0; v < 4; v++) acc[i][j][v] = 0.0f;

  auto issue_load = [&](int c) {
    int s = c & 1, kt = c * 64;
    uint32_t base = sb + s * H_STAGE;
    load_tile<DD, 64>(base, g_xb, m0, kt);
#pragma unroll
    for (int p = 0; p < 2; p++)
      load_tile<DD, 128>(base + 8192 + 16384 * p, g_Wh[p], 0, kt);
    asm volatile("cp.async.commit_group;" ::: "memory");
  };

  issue_load(0); issue_load(1);

#pragma unroll 1
  for (int c = 0; c < 64; c++) {
    if (c + 1 < 64) asm volatile("cp.async.wait_group 1;" ::: "memory");
    else            asm volatile("cp.async.wait_group 0;" ::: "memory");
    __syncthreads();
    uint32_t base = sb + (uint32_t)(c & 1) * H_STAGE;
#pragma unroll
    for (int kk = 0; kk < 4; kk++) {
      uint32_t a[2][4];
#pragma unroll
      for (int i = 0; i < 2; i++)
        ldsm4(a[i], base + sw128(offA[i] + kk * 32));
#pragma unroll
      for (int p = 0; p < 2; p++) {
        uint32_t bb = base + 8192u + 16384u * p;
#pragma unroll
        for (int jb = 0; jb < 2; jb++) {
          uint32_t b[4];
          ldsm4(b, bb + sw128(offB[jb] + kk * 32));
#pragma unroll
          for (int i = 0; i < 2; i++) {
            mma_bf16(acc[i][jb * 2 + 0], a[i], b[0], b[1]);
            mma_bf16(acc[i][jb * 2 + 1], a[i], b[2], b[3]);
          }
        }
      }
    }
    __syncthreads();
    if (c + 2 < 64) issue_load(c + 2);
  }

  // epilogue: bias + softplus and/or threefry sample into g_hb
  double sp = 0.0;
  const __nv_bfloat16 onev = __float2bfloat16(1.0f);
  const __nv_bfloat16 zerov = __float2bfloat16(0.0f);
#pragma unroll
  for (int i = 0; i < 2; i++) {
#pragma unroll
    for (int j = 0; j < 4; j++) {
      int col = wn * 32 + j * 8 + 2 * tq;
      float2 b2 = *(const float2 *)&bh_[col];
#pragma unroll
      for (int h = 0; h < 2; h++) {
        int gr = m0 + wm * 32 + i * 16 + q + h * 8;
        float l0 = acc[i][j][2 * h + 0] + b2.x;
        float l1 = acc[i][j][2 * h + 1] + b2.y;
        if (acc_slot >= 0)
          sp += (double)softplusf_(l0) + (double)softplusf_(l1);
        if (do_sample) {
          float p0 = fast_sigmoid(l0), p1 = fast_sigmoid(l1);
          uint32_t idx0 = (uint32_t)gr * (uint32_t)HH + (uint32_t)col;
          float u0 = jax_uniform01(k0, k1, idx0);
          float u1 = jax_uniform01(k0, k1, idx0 + 1u);
          __nv_bfloat162 v;
          v.x = (u0 < p0) ? onev : zerov;
          v.y = (u1 < p1) ? onev : zerov;
          *(__nv_bfloat162 *)&g_hb[(size_t)gr * HH + col] = v;
        }
      }
    }
  }
  if (acc_slot >= 0) {
#pragma unroll
    for (int o = 16; o > 0; o >>= 1) sp += __shfl_down_sync(0xffffffffu, sp, o);
    if (l == 0) atomicAdd(&g_acc[acc_slot], sp);
  }
}

// =============================================================
// x-pass (R14 fused config + mbase): lin = h @ W^T + bx; sample in place.
// CTA 64(M) x 64(N); 4 CTAs/SM (64-reg cap); all loads upfront.
// staging reuses B region after compute (sync-guarded).
// =============================================================
static constexpr int X_STG_PITCH = 136;
static constexpr int X_SMEM = 49152;

__global__ void __launch_bounds__(256, 4)
gemm_x_kernel(const float *__restrict__ bx_, uint32_t k0, uint32_t k1,
              int bx_slot, int mbase) {
  extern __shared__ char smem[];
  uint32_t sb = smem_u32(smem);
  const int t = threadIdx.x, wid = t >> 5, l = t & 31;
  const int wm = wid & 1, wn = wid >> 1;
  const int m0 = mbase + blockIdx.x * 64, n0 = blockIdx.y * 64;
  const int q = l >> 2, tq = l & 3;

  uint32_t offA[2], offB;
#pragma unroll
  for (int i = 0; i < 2; i++)
    offA[i] = (uint32_t)((wm * 32 + i * 16 + (l & 15)) * 128 + ((l >> 4) & 1) * 16);
  offB = (uint32_t)((wn * 16 + (l & 7) + ((l >> 4) & 1) * 8) * 128 +
                    ((l >> 3) & 1) * 16);

#pragma unroll
  for (int kc = 0; kc < 2; kc++) {
    load_tile<HH, 64>(sb + kc * 8192, g_hb, m0, kc * 64);
#pragma unroll
    for (int p = 0; p < 2; p++)
      load_tile<HH, 64>(sb + 16384 + kc * 16384 + p * 8192, g_Wx[p], n0, kc * 64);
  }
  asm volatile("cp.async.commit_group;" ::: "memory");

  float acc[2][2][4];
#pragma unroll
  for (int i = 0; i < 2; i++)
#pragma unroll
    for (int j = 0; j < 2; j++)
#pragma unroll
      for (int v = 0; v < 4; v++) acc[i][j][v] = 0.0f;

  asm volatile("cp.async.wait_group 0;" ::: "memory");
  __syncthreads();

#pragma unroll
  for (int kc = 0; kc < 2; kc++) {
    uint32_t abase = sb + (uint32_t)kc * 8192;
    uint32_t bbase = sb + 16384u + (uint32_t)kc * 16384;
#pragma unroll
    for (int kk = 0; kk < 4; kk++) {
      uint32_t a[2][4];
#pragma unroll
      for (int i = 0; i < 2; i++)
        ldsm4(a[i], abase + sw128(offA[i] + kk * 32));
#pragma unroll
      for (int p = 0; p < 2; p++) {
        uint32_t b[4];
        ldsm4(b, bbase + p * 8192u + sw128(offB + kk * 32));
#pragma unroll
        for (int i = 0; i < 2; i++) {
          mma_bf16(acc[i][0], a[i], b[0], b[1]);
          mma_bf16(acc[i][1], a[i], b[2], b[3]);
        }
      }
    }
  }
  __syncthreads();  // B fully consumed before staging overwrites it

  double spb = 0.0;
  const __nv_bfloat16 onev = __float2bfloat16(1.0f);
  const __nv_bfloat16 zerov = __float2bfloat16(0.0f);
  char *stg = smem + 16384;
#pragma unroll
  for (int j = 0; j < 2; j++) {
    int col = wn * 16 + j * 8 + 2 * tq;
    float2 b2 = *(const float2 *)&bx_[n0 + col];
#pragma unroll
    for (int i = 0; i < 2; i++) {
#pragma unroll
      for (int h = 0; h < 2; h++) {
        int row = wm * 32 + i * 16 + q + h * 8;
        float l0 = acc[i][j][2 * h + 0] + b2.x;
        float l1 = acc[i][j][2 * h + 1] + b2.y;
        float p0 = fast_sigmoid(l0), p1 = fast_sigmoid(l1);
        uint32_t idx0 = (uint32_t)(m0 + row) * (uint32_t)DD + (uint32_t)(n0 + col);
        float u0 = jax_uniform01(k0, k1, idx0);
        float u1 = jax_uniform01(k0, k1, idx0 + 1u);
        bool s0 = (u0 < p0), s1 = (u1 < p1);
        if (bx_slot >= 0) {
          if (s0) spb += (double)b2.x;
          if (s1) spb += (double)b2.y;
        }
        __nv_bfloat162 v;
        v.x = s0 ? onev : zerov;
        v.y = s1 ? onev : zerov;
        *(__nv_bfloat162 *)(stg + row * X_STG_PITCH + col * 2) = v;
      }
    }
  }
  if (bx_slot >= 0) {
#pragma unroll
    for (int o = 16; o > 0; o >>= 1) spb += __shfl_down_sync(0xffffffffu, spb, o);
    if (l == 0) atomicAdd(&g_acc[bx_slot], spb);
  }
  __syncthreads();
#pragma unroll
  for (int i2 = 0; i2 < 4; i2++) {
    int idx = t + 256 * i2;
    int rr = idx >> 4, c8 = idx & 15;
    uint64_t v = *(const uint64_t *)(stg + rr * X_STG_PITCH + c8 * 8);
    *(uint64_t *)&g_xb[(size_t)(m0 + rr) * DD + n0 + c8 * 4] = v;
  }
}

// ---------------- prep: conv (+x.bx) and wsplit merged ----------------
__global__ void prep_kernel(const float *__restrict__ x,
                            const float *__restrict__ bx,
                            const float *__restrict__ W) {
  if (blockIdx.x < 1024) {
    size_t n = (size_t)BB * DD / 4;
    double s = 0.0;
    for (size_t i = (size_t)blockIdx.x * blockDim.x + threadIdx.x; i < n;
         i += (size_t)1024 * blockDim.x) {
      float4 v = ((const float4 *)x)[i];
      ushort4 o;
      o.x = __bfloat16_as_ushort(__float2bfloat16(v.x));
      o.y = __bfloat16_as_ushort(__float2bfloat16(v.y));
      o.z = __bfloat16_as_ushort(__float2bfloat16(v.z));
      o.w = __bfloat16_as_ushort(__float2bfloat16(v.w));
      ((ushort4 *)g_xb)[i] = o;
      uint32_t d = (uint32_t)((i * 4) & (DD - 1));
      const float4 b4 = *(const float4 *)&bx[d];
      s += (double)(v.x * b4.x + v.y * b4.y) + (double)(v.z * b4.z + v.w * b4.w);
    }
#pragma unroll
    for (int off = 16; off > 0; off >>= 1)
      s += __shfl_down_sync(0xffffffffu, s, off);
    if ((threadIdx.x & 31) == 0) atomicAdd(&g_acc[2], s);
  } else {
    int n = DD * HH;
    for (int i = (blockIdx.x - 1024) * blockDim.x + threadIdx.x; i < n;
         i += 256 * blockDim.x) {
      float w = W[i];
      __nv_bfloat16 b0 = __float2bfloat16(w);
      float r1 = w - __bfloat162float(b0);
      __nv_bfloat16 b1 = __float2bfloat16(r1);
      g_Wx[0][i] = b0; g_Wx[1][i] = b1;
      int d = i >> 7, h = i & 127;
      int j = h * DD + d;
      g_Wh[0][j] = b0; g_Wh[1][j] = b1;
    }
  }
}

__global__ void zero_acc_kernel() {
  if (threadIdx.x < 4) g_acc[threadIdx.x] = 0.0;
}

__global__ void finalize_kernel(float *out) {
  double cd = (-g_acc[0] - g_acc[2] + g_acc[1] + g_acc[3]) / (double)BB;
  out[0] = (float)cd;
}

// =============================================================
extern "C" void kernel_launch(void *const *d_in, const int *in_sizes, int n_in,
                              void *d_out, int out_size) {
  (void)in_sizes; (void)n_in; (void)out_size;
  const float *x  = (const float *)d_in[0];
  const float *W  = (const float *)d_in[1];
  const float *bx = (const float *)d_in[2];
  const float *bh = (const float *)d_in[3];

  static int inited = 0;
  static cudaStream_t s1;
  static cudaEvent_t evFork, evSeed, evJoin;
  if (!inited) {
    cudaFuncSetAttribute(gemm_h_kernel,
                         cudaFuncAttributeMaxDynamicSharedMemorySize, H_SMEM);
    cudaFuncSetAttribute(gemm_x_kernel,
                         cudaFuncAttributeMaxDynamicSharedMemorySize, X_SMEM);
    cudaStreamCreateWithFlags(&s1, cudaStreamNonBlocking);
    cudaEventCreateWithFlags(&evFork, cudaEventDisableTiming);
    cudaEventCreateWithFlags(&evSeed, cudaEventDisableTiming);
    cudaEventCreateWithFlags(&evJoin, cudaEventDisableTiming);
    inited = 1;
  }

  zero_acc_kernel<<<1, 32>>>();
  prep_kernel<<<1280, 256>>>(x, bx, W);

  uint32_t hk[5][2], xk[4][2];
  for (int i = 0; i < 5; i++) tf2x32(0u, 42u, 0u, (uint32_t)(2 * i), hk[i][0], hk[i][1]);
  for (int i = 0; i < 4; i++) tf2x32(0u, 42u, 0u, (uint32_t)(2 * i + 1), xk[i][0], xk[i][1]);

  dim3 grdh(HALF / 64, 1);
  dim3 grdx(HALF / 64, DD / 64);

  // fork: stream 1 (half B) branches off after prep
  cudaEventRecord(evFork, 0);
  cudaStreamWaitEvent(s1, evFork, 0);

  // --- half A (rows 0..HALF) on default stream ---
  gemm_h_kernel<<<grdh, 256, H_SMEM>>>(bh, hk[0][0], hk[0][1], 1, 0, 0);
  cudaEventRecord(evSeed, 0);  // seed one-stage offset for half B
  for (int i = 0; i < 4; i++) {
    gemm_x_kernel<<<grdx, 256, X_SMEM>>>(bx, xk[i][0], xk[i][1],
                                         (i == 3) ? 3 : -1, 0);
    if (i < 3)
      gemm_h_kernel<<<grdh, 256, H_SMEM>>>(bh, hk[i + 1][0], hk[i + 1][1], 1, -1, 0);
  }
  gemm_h_kernel<<<grdh, 256, H_SMEM>>>(bh, 0u, 0u, 0, 1, 0);

  // --- half B (rows HALF..BB) on stream 1, offset by one stage ---
  cudaStreamWaitEvent(s1, evSeed, 0);
  gemm_h_kernel<<<grdh, 256, H_SMEM, s1>>>(bh, hk[0][0], hk[0][1], 1, 0, HALF);
  for (int i = 0; i < 4; i++) {
    gemm_x_kernel<<<grdx, 256, X_SMEM, s1>>>(bx, xk[i][0], xk[i][1],
                                             (i == 3) ? 3 : -1, HALF);
    if (i < 3)
      gemm_h_kernel<<<grdh, 256, H_SMEM, s1>>>(bh, hk[i + 1][0], hk[i + 1][1],
                                               1, -1, HALF);
  }
  gemm_h_kernel<<<grdh, 256, H_SMEM, s1>>>(bh, 0u, 0u, 0, 1, HALF);

  // join
  cudaEventRecord(evJoin, s1);
  cudaStreamWaitEvent(0, evJoin, 0);
  finalize_kernel<<<1, 1>>>((float *)d_out);
}